// round 9
// baseline (speedup 1.0000x reference)
#include <cuda_runtime.h>
#include <cstdint>

#define N_BINS 1000
#define EPS_F 1e-4f
#define TPB 256
#define ROWS_PER_CHUNK 512                 // 2 rows per thread per chunk
#define CHUNK_WORDS (ROWS_PER_CHUNK * 3)   // 1536 int32
#define CHUNK_BYTES (CHUNK_WORDS * 4)      // 6144 B, 16B-multiple for TMA
#define NSTAGES 4
// smem: 12KB table + 4*6KB buffers = ~36.4KB -> >=5 CTAs/SM.
// 148 SMs x 5 = 740 blocks = one wave.
#define NBLOCKS 740

__device__ __forceinline__ uint32_t smem_u32(const void* p) {
    return (uint32_t)__cvta_generic_to_shared(p);
}

__device__ __forceinline__ void mbar_init(uint32_t mbar, uint32_t count) {
    asm volatile("mbarrier.init.shared.b64 [%0], %1;" :: "r"(mbar), "r"(count)
                 : "memory");
}

__device__ __forceinline__ void tma_issue(uint32_t dst_smem,
                                          const void* src_gmem,
                                          uint32_t mbar) {
    asm volatile("mbarrier.arrive.expect_tx.shared.b64 _, [%0], %1;"
                 :: "r"(mbar), "r"((uint32_t)CHUNK_BYTES) : "memory");
    asm volatile(
        "cp.async.bulk.shared::cta.global.mbarrier::complete_tx::bytes "
        "[%0], [%1], %2, [%3];"
        :: "r"(dst_smem), "l"(src_gmem), "r"((uint32_t)CHUNK_BYTES),
           "r"(mbar)
        : "memory");
}

__device__ __forceinline__ void mbar_wait(uint32_t mbar, uint32_t phase) {
    asm volatile(
        "{\n\t"
        ".reg .pred P;\n\t"
        "W_%=:\n\t"
        "mbarrier.try_wait.parity.acquire.cta.shared::cta.b64 P, [%0], %1, 0x989680;\n\t"
        "@P bra D_%=;\n\t"
        "bra W_%=;\n\t"
        "D_%=:\n\t"
        "}"
        :: "r"(mbar), "r"(phase) : "memory");
}

// ---------------------------------------------------------------------------
// Persistent fused kernel:
//   1) per-block 3x1000 sigmoid table in shared memory
//   2) 4-stage cp.async.bulk (TMA) pipeline staging the int32 index stream
//      into smem (keeps ~3 chunks/CTA in flight -> ~13MB outstanding
//      chip-wide, saturating the DRAM latency-BW product), then
//      conflict-free LDS.32 index reads + table gathers + coalesced STG.32.
// ---------------------------------------------------------------------------
__global__ void __launch_bounds__(TPB, 5)
pm_fused_kernel(const float* __restrict__ bin_centers,
                const float* __restrict__ lower_bounds,
                const float* __restrict__ upper_bounds,
                const int* __restrict__ idx_g,
                float* __restrict__ out,
                long long n_rows) {
    __shared__ float sS[3 * N_BINS];
    __shared__ __align__(16) unsigned sIdx[NSTAGES][CHUNK_WORDS];
    __shared__ __align__(8) unsigned long long sMbar[NSTAGES];

    // ---- table build: S[j][b] = sigmoid((ub_j - logit(t_b)) * inv_j) ----
    float hi[3], inv[3];
#pragma unroll
    for (int j = 0; j < 3; j++) {
        float l = lower_bounds[j];
        float u = upper_bounds[j];
        float lo = fminf(l, u);
        float h  = fmaxf(l, u);
        hi[j]  = h;
        inv[j] = 1.0f / (h - lo + EPS_F);
    }
    for (int b = threadIdx.x; b < N_BINS; b += TPB) {
        float t = __ldg(bin_centers + b);
        float g = __logf(t / (1.0f - t));
#pragma unroll
        for (int j = 0; j < 3; j++) {
            float x = (hi[j] - g) * inv[j];
            sS[j * N_BINS + b] = 1.0f / (1.0f + __expf(-x));
        }
    }

    const float* __restrict__ S0 = sS;
    const float* __restrict__ S1 = sS + N_BINS;
    const float* __restrict__ S2 = sS + 2 * N_BINS;

    uint32_t buf_a[NSTAGES], mb_a[NSTAGES];
#pragma unroll
    for (int k = 0; k < NSTAGES; k++) {
        buf_a[k] = smem_u32(sIdx[k]);
        mb_a[k]  = smem_u32(&sMbar[k]);
    }

    if (threadIdx.x == 0) {
#pragma unroll
        for (int k = 0; k < NSTAGES; k++) mbar_init(mb_a[k], 1);
    }
    __syncthreads();

    const long long n_chunks = n_rows / ROWS_PER_CHUNK;
    const long long G = gridDim.x;
    const long long c0 = blockIdx.x;

    // Prologue: arm all stages.
    if (threadIdx.x == 0) {
#pragma unroll
        for (int k = 0; k < NSTAGES; k++) {
            long long c = c0 + (long long)k * G;
            if (c < n_chunks)
                tma_issue(buf_a[k], idx_g + c * CHUNK_WORDS, mb_a[k]);
        }
    }

    unsigned phase[NSTAGES];
#pragma unroll
    for (int k = 0; k < NSTAGES; k++) phase[k] = 0u;

    int s = 0;
    for (long long c = c0; c < n_chunks; c += G) {
        mbar_wait(mb_a[s], phase[s]);
        phase[s] ^= 1u;

        const unsigned* __restrict__ ib = sIdx[s];
        long long rbase = c * ROWS_PER_CHUNK;

        // 2 rows per thread; index-word bank = (3*lane + k) % 32 ->
        // conflict-free LDS; output stores unit-stride coalesced.
        {
            int lr0 = threadIdx.x;
            int lr1 = threadIdx.x + TPB;
            unsigned a0 = ib[3 * lr0 + 0];
            unsigned b0 = ib[3 * lr0 + 1];
            unsigned c0i = ib[3 * lr0 + 2];
            unsigned a1 = ib[3 * lr1 + 0];
            unsigned b1 = ib[3 * lr1 + 1];
            unsigned c1i = ib[3 * lr1 + 2];
            float r0 = S0[a0] * S1[b0] * S2[c0i];
            float r1 = S0[a1] * S1[b1] * S2[c1i];
            out[rbase + lr0] = r0;
            out[rbase + lr1] = r1;
        }
        __syncthreads();  // all threads done reading buffer s

        long long cn = c + (long long)NSTAGES * G;
        if (threadIdx.x == 0 && cn < n_chunks)
            tma_issue(buf_a[s], idx_g + cn * CHUNK_WORDS, mb_a[s]);
        s = (s + 1) & (NSTAGES - 1);
    }

    // ---- tail rows (n_rows % ROWS_PER_CHUNK; zero for this problem) ----
    if (blockIdx.x == 0) {
        for (long long r = n_chunks * ROWS_PER_CHUNK + threadIdx.x;
             r < n_rows; r += TPB) {
            int a = idx_g[3 * r + 0];
            int b = idx_g[3 * r + 1];
            int ci = idx_g[3 * r + 2];
            out[r] = S0[a] * S1[b] * S2[ci];
        }
    }
}

extern "C" void kernel_launch(void* const* d_in, const int* in_sizes, int n_in,
                              void* d_out, int out_size) {
    const float* bin_centers  = (const float*)d_in[0];
    const int*   obs_idx      = (const int*)d_in[1];   // JAX x64-off: int64 -> int32
    const float* lower_bounds = (const float*)d_in[2];
    const float* upper_bounds = (const float*)d_in[3];
    float* out = (float*)d_out;

    long long n = out_size;

    int blocks = NBLOCKS;
    long long n_chunks = n / ROWS_PER_CHUNK;
    if (n_chunks > 0 && n_chunks < blocks) blocks = (int)n_chunks;
    if (blocks < 1) blocks = 1;

    pm_fused_kernel<<<blocks, TPB>>>(bin_centers, lower_bounds, upper_bounds,
                                     obs_idx, out, n);
}

// round 10
// speedup vs baseline: 1.2326x; 1.2326x over previous
#include <cuda_runtime.h>
#include <cstdint>

#define N_BINS 1000
#define EPS_F 1e-4f
#define TPB 256
// 48-reg kernel -> 5 resident blocks/SM; 148 SMs x 5 = 740 = one wave.
#define NBLOCKS 740

// ---------------------------------------------------------------------------
// Fused persistent kernel (best-measured config, round 6: 25.1us kernel):
//   1) per-block build of the 3x1000 sigmoid table in shared memory
//   2) depth-2 software-pipelined grid-stride gather-product loop
// plus streaming cache hints: __ldcs on the read-once index stream,
// __stcs on the write-once output stream (keeps L2 clean for reads).
//
// Quad layout (3 x uint4 per 4 rows of 3 int32 indices):
//   v0 = [i0.a, i0.b, i0.c, i1.a]
//   v1 = [i1.b, i1.c, i2.a, i2.b]
//   v2 = [i2.c, i3.a, i3.b, i3.c]
// ---------------------------------------------------------------------------
__global__ void __launch_bounds__(TPB, 5)
pm_fused_kernel(const float* __restrict__ bin_centers,
                const float* __restrict__ lower_bounds,
                const float* __restrict__ upper_bounds,
                const uint4* __restrict__ idx_v,
                float4* __restrict__ out_v,
                const int* __restrict__ idx_s,   // scalar view for tail
                float* __restrict__ out_s,
                int n_quads, int n_rows) {
    __shared__ float sS[3 * N_BINS];

    // ---- table build: S[j][b] = sigmoid((ub_j - logit(t_b)) * inv_j) ----
    float hi[3], inv[3];
#pragma unroll
    for (int j = 0; j < 3; j++) {
        float l = lower_bounds[j];
        float u = upper_bounds[j];
        float lo = fminf(l, u);
        float h  = fmaxf(l, u);
        hi[j]  = h;
        inv[j] = 1.0f / (h - lo + EPS_F);
    }
    for (int b = threadIdx.x; b < N_BINS; b += TPB) {
        float t = __ldg(bin_centers + b);
        float g = __logf(t / (1.0f - t));
#pragma unroll
        for (int j = 0; j < 3; j++) {
            float x = (hi[j] - g) * inv[j];
            sS[j * N_BINS + b] = 1.0f / (1.0f + __expf(-x));
        }
    }
    __syncthreads();

    const float* __restrict__ S0 = sS;
    const float* __restrict__ S1 = sS + N_BINS;
    const float* __restrict__ S2 = sS + 2 * N_BINS;

    // ---- depth-2 pipelined grid-stride loop over quads ----
    const int stride = gridDim.x * TPB;
    int q0 = blockIdx.x * TPB + threadIdx.x;
    int q1 = q0 + stride;
    int q2 = q1 + stride;

    uint4 a0, a1, a2;   // quad q0
    uint4 b0, b1, b2;   // quad q1

    if (q0 < n_quads) {
        const uint4* p = idx_v + (size_t)q0 * 3;
        a0 = __ldcs(p + 0);
        a1 = __ldcs(p + 1);
        a2 = __ldcs(p + 2);
    }
    if (q1 < n_quads) {
        const uint4* p = idx_v + (size_t)q1 * 3;
        b0 = __ldcs(p + 0);
        b1 = __ldcs(p + 1);
        b2 = __ldcs(p + 2);
    }

    while (q2 < n_quads) {
        // Prefetch quad q2 (two iterations ahead of the one being computed).
        const uint4* p = idx_v + (size_t)q2 * 3;
        uint4 c0 = __ldcs(p + 0);
        uint4 c1 = __ldcs(p + 1);
        uint4 c2 = __ldcs(p + 2);

        float4 o;
        o.x = S0[a0.x] * S1[a0.y] * S2[a0.z];
        o.y = S0[a0.w] * S1[a1.x] * S2[a1.y];
        o.z = S0[a1.z] * S1[a1.w] * S2[a2.x];
        o.w = S0[a2.y] * S1[a2.z] * S2[a2.w];
        __stcs(out_v + q0, o);

        a0 = b0; a1 = b1; a2 = b2;
        b0 = c0; b1 = c1; b2 = c2;
        q0 = q1; q1 = q2; q2 += stride;
    }

    // Drain: at most two quads left in registers.
    if (q0 < n_quads) {
        float4 o;
        o.x = S0[a0.x] * S1[a0.y] * S2[a0.z];
        o.y = S0[a0.w] * S1[a1.x] * S2[a1.y];
        o.z = S0[a1.z] * S1[a1.w] * S2[a2.x];
        o.w = S0[a2.y] * S1[a2.z] * S2[a2.w];
        __stcs(out_v + q0, o);
    }
    if (q1 < n_quads) {
        float4 o;
        o.x = S0[b0.x] * S1[b0.y] * S2[b0.z];
        o.y = S0[b0.w] * S1[b1.x] * S2[b1.y];
        o.z = S0[b1.z] * S1[b1.w] * S2[b2.x];
        o.w = S0[b2.y] * S1[b2.z] * S2[b2.w];
        __stcs(out_v + q1, o);
    }

    // ---- scalar tail (n_rows % 4 != 0; never taken for this problem) ----
    int tail_start = n_quads * 4;
    if (blockIdx.x == 0) {
        int r = tail_start + threadIdx.x;
        if (r < n_rows) {
            int a = idx_s[3 * (size_t)r + 0];
            int b = idx_s[3 * (size_t)r + 1];
            int c = idx_s[3 * (size_t)r + 2];
            out_s[r] = S0[a] * S1[b] * S2[c];
        }
    }
}

extern "C" void kernel_launch(void* const* d_in, const int* in_sizes, int n_in,
                              void* d_out, int out_size) {
    const float* bin_centers  = (const float*)d_in[0];
    const int*   obs_idx      = (const int*)d_in[1];   // JAX x64-off: int64 -> int32
    const float* lower_bounds = (const float*)d_in[2];
    const float* upper_bounds = (const float*)d_in[3];
    float* out = (float*)d_out;

    int n = out_size;
    int n_quads = n / 4;

    int blocks = NBLOCKS;
    int max_needed = (n_quads + TPB - 1) / TPB;
    if (max_needed < 1) max_needed = 1;
    if (blocks > max_needed) blocks = max_needed;

    pm_fused_kernel<<<blocks, TPB>>>(bin_centers, lower_bounds, upper_bounds,
                                     (const uint4*)obs_idx, (float4*)out,
                                     obs_idx, out, n_quads, n);
}